// round 15
// baseline (speedup 1.0000x reference)
#include <cuda_runtime.h>
#include <cuda_fp16.h>

#define L    4096
#define NK   40

// ---------------------------------------------------------------------------
// Global scratch (static; no allocations)
__device__ __half g_phi[NK * L];                    // fp16 phi[lag], [k][lag]
__device__ __half g_Mh[NK * 128 * 64];              // [k][o-stack][d]: rows 0-63 Mp^T, 64-127 Mm^T
__device__ __half g_xh[2 * L * 64];                 // fp16 hi of x
__device__ __half g_xl[2 * L * 64];                 // fp16 lo of x
__device__ __half g_B[(size_t)NK * 2 * 128 * L];    // [k][par][n][s] fp16
// par=0: B'[s]  = (s even ? Zp+Zm : Zp-Zm)   (feeds even-t rows)
// par=1: B''[s] = (s even ? Zp-Zm : Zp+Zm)   (feeds odd-t rows)

// ---------------------------------------------------------------------------
__device__ __forceinline__ unsigned smem_u32(const void* p) {
    unsigned a;
    asm("{ .reg .u64 t; cvta.to.shared.u64 t, %1; cvt.u32.u64 %0, t; }" : "=r"(a) : "l"(p));
    return a;
}
__device__ __forceinline__ void ldsm4(unsigned& r0, unsigned& r1, unsigned& r2,
                                      unsigned& r3, unsigned addr) {
    asm volatile("ldmatrix.sync.aligned.m8n8.x4.shared.b16 {%0,%1,%2,%3}, [%4];"
                 : "=r"(r0), "=r"(r1), "=r"(r2), "=r"(r3) : "r"(addr));
}
__device__ __forceinline__ void hmma(float* c, unsigned a0, unsigned a1, unsigned a2,
                                     unsigned a3, unsigned b0, unsigned b1) {
    asm volatile(
        "mma.sync.aligned.m16n8k16.row.col.f32.f16.f16.f32 "
        "{%0,%1,%2,%3},{%4,%5,%6,%7},{%8,%9},{%0,%1,%2,%3};"
        : "+f"(c[0]), "+f"(c[1]), "+f"(c[2]), "+f"(c[3])
        : "r"(a0), "r"(a1), "r"(a2), "r"(a3), "r"(b0), "r"(b1));
}
__device__ __forceinline__ void cp16(unsigned dst, const void* src) {
    asm volatile("cp.async.ca.shared.global [%0], [%1], 16;" :: "r"(dst), "l"(src));
}

// ---------------------------------------------------------------------------
// prep: phi fp16
__global__ void k_prep(const float* __restrict__ phi) {
    int gid = blockIdx.x * 256 + threadIdx.x;
    if (gid >= NK * L) return;
    int k = gid >> 12, lag = gid & (L - 1);
    g_phi[(k << 12) + lag] = __float2half_rn(phi[lag * NK + k]);
}
// prep: M transposed+stacked fp16  (g_Mh[k][o][d]=Mp[k][d][o]; [k][64+o][d]=Mm)
__global__ void k_prep_m(const float* __restrict__ Mp, const float* __restrict__ Mm) {
    int gid = blockIdx.x * 256 + threadIdx.x;
    if (gid >= NK * 64 * 64) return;
    int k = gid >> 12, rem = gid & 4095, d = rem >> 6, o = rem & 63;
    g_Mh[((size_t)k * 128 + o) * 64 + d]      = __float2half_rn(Mp[gid]);
    g_Mh[((size_t)k * 128 + 64 + o) * 64 + d] = __float2half_rn(Mm[gid]);
}
// prep: x hi/lo fp16 split
__global__ void k_prep_x(const float* __restrict__ x) {
    int gid = blockIdx.x * 256 + threadIdx.x;
    if (gid >= 2 * L * 64) return;
    float v = x[gid];
    __half h = __float2half_rn(v);
    g_xh[gid] = h;
    g_xl[gid] = __float2half_rn(v - __half2float(h));
}

// ---------------------------------------------------------------------------
// AR term (initializes out), register-tiled: thread = 4t x 8o, float4 both ways.
// CTA = (t-block of 128, batch b). smem: x rows [tbase-2, tbase+128) + M.
#define AR_XROWS 130
#define AR_OFF_M (AR_XROWS * 64 * 4)                 // 33280
#define AR_SMEM  (AR_OFF_M + 3 * 64 * 64 * 4)        // 82432

__global__ void __launch_bounds__(256) k_ar(const float* __restrict__ x,
                                            const float* __restrict__ M,
                                            float* __restrict__ out) {
    extern __shared__ char arsm[];
    float* sx = (float*)arsm;                 // [130][64]
    float* sM = (float*)(arsm + AR_OFF_M);    // [(i*64+d)*64 + o]
    int tid = threadIdx.x;
    int tb = blockIdx.x, b = blockIdx.y;
    int tbase = tb << 7;

    // load M
    for (int idx = tid; idx < 64 * 64 * 3; idx += 256) {
        int o = idx / 192, rem = idx % 192, d = rem / 3, i = rem % 3;
        sM[(i * 64 + d) * 64 + o] = M[idx];
    }
    // load x rows tbase-2 .. tbase+127 (zero below 0)
    const float* xb = x + ((size_t)b << 18);
    for (int idx = tid; idx < AR_XROWS * 64; idx += 256) {
        int r = idx >> 6, c = idx & 63;
        int t = tbase + r - 2;
        sx[idx] = (t >= 0) ? xb[(t << 6) + c] : 0.f;
    }
    __syncthreads();

    int tx = tid & 7, ty = tid >> 3;          // o-block, t-block
    int trow0 = ty * 4, ocol = tx * 8;

    float4 acc[4][2];
    #pragma unroll
    for (int i = 0; i < 4; i++) {
        acc[i][0] = make_float4(0.f, 0.f, 0.f, 0.f);
        acc[i][1] = make_float4(0.f, 0.f, 0.f, 0.f);
    }

    const float4* sx4 = (const float4*)sx;
    const float4* sM4 = (const float4*)sM;

    #pragma unroll
    for (int i = 0; i < 3; i++) {
        #pragma unroll 4
        for (int db = 0; db < 16; db++) {
            float4 xv[4];
            #pragma unroll
            for (int tt = 0; tt < 4; tt++)
                xv[tt] = sx4[(trow0 + tt + 2 - i) * 16 + db];
            float4 mv[4][2];
            #pragma unroll
            for (int dd = 0; dd < 4; dd++) {
                int mrow = (i * 64 + db * 4 + dd) * 16 + tx * 2;
                mv[dd][0] = sM4[mrow];
                mv[dd][1] = sM4[mrow + 1];
            }
            #pragma unroll
            for (int tt = 0; tt < 4; tt++) {
                float xs0 = xv[tt].x, xs1 = xv[tt].y, xs2 = xv[tt].z, xs3 = xv[tt].w;
                #pragma unroll
                for (int v = 0; v < 2; v++) {
                    acc[tt][v].x += xs0 * mv[0][v].x + xs1 * mv[1][v].x
                                  + xs2 * mv[2][v].x + xs3 * mv[3][v].x;
                    acc[tt][v].y += xs0 * mv[0][v].y + xs1 * mv[1][v].y
                                  + xs2 * mv[2][v].y + xs3 * mv[3][v].y;
                    acc[tt][v].z += xs0 * mv[0][v].z + xs1 * mv[1][v].z
                                  + xs2 * mv[2][v].z + xs3 * mv[3][v].z;
                    acc[tt][v].w += xs0 * mv[0][v].w + xs1 * mv[1][v].w
                                  + xs2 * mv[2][v].w + xs3 * mv[3][v].w;
                }
            }
        }
    }

    #pragma unroll
    for (int tt = 0; tt < 4; tt++) {
        int t = tbase + trow0 + tt;
        float* p = out + ((((size_t)b << 12) + t) << 6) + ocol;
        *(float4*)p = acc[tt][0];
        *(float4*)(p + 4) = acc[tt][1];
    }
}

// ---------------------------------------------------------------------------
// HMMA Z build. CTA = (s-tile of 128, batch b, filter k). All operands
// pre-converted fp16 in global; cp.async into padded smem, MMA, parity-fold.
#define ZROWB   144
#define ZOFF_A  0
#define ZOFF_BH (128 * ZROWB)
#define ZOFF_BL (2 * 128 * ZROWB)
#define ZOFF_ST (3 * 128 * ZROWB)                // 64 x 132 fp32 stage
#define ZSMEM   (ZOFF_ST + 64 * 132 * 4)         // 89088

__global__ void __launch_bounds__(256) k_z() {
    extern __shared__ char smem[];
    unsigned sbu = smem_u32(smem);
    int tid = threadIdx.x, wid = tid >> 5, lane = tid & 31;
    int stile = blockIdx.x, b = blockIdx.y, k = blockIdx.z;
    int mg = wid >> 2, ng = wid & 3;   // warp: m-half (Zp/Zm), s-group of 32

    // cp.async: A (M stack), Bh, Bl (x split) — 128 rows x 128B each
    const char* srcA = (const char*)(g_Mh + (size_t)k * 8192);
    const char* srcH = (const char*)(g_xh + (((size_t)(b << 12) + (stile << 7)) << 6));
    const char* srcL = (const char*)(g_xl + (((size_t)(b << 12) + (stile << 7)) << 6));
    for (int i = tid; i < 1024; i += 256) {
        int row = i >> 3, seg = (i & 7) * 16;
        cp16(sbu + ZOFF_A + row * ZROWB + seg, srcA + row * 128 + seg);
        cp16(sbu + ZOFF_BH + row * ZROWB + seg, srcH + row * 128 + seg);
        cp16(sbu + ZOFF_BL + row * ZROWB + seg, srcL + row * 128 + seg);
    }
    asm volatile("cp.async.commit_group;");
    asm volatile("cp.async.wait_group 0;");
    __syncthreads();

    unsigned aOff = sbu + ZOFF_A + (unsigned)((mg * 64 + (lane & 15)) * ZROWB + (lane >> 4) * 16);
    unsigned bOff = (unsigned)((ng * 32 + (lane & 7) + ((lane >> 4) & 1) * 8) * ZROWB
                               + ((lane >> 3) & 1) * 16);
    unsigned bH = sbu + ZOFF_BH + bOff, bL = sbu + ZOFF_BL + bOff;

    float c[4][4][4];
    #pragma unroll
    for (int i = 0; i < 4; i++)
        #pragma unroll
        for (int j = 0; j < 4; j++)
            #pragma unroll
            for (int q = 0; q < 4; q++) c[i][j][q] = 0.f;

    #pragma unroll
    for (int ks = 0; ks < 4; ks++) {
        unsigned ko = ks * 32;
        unsigned Ar[4][4], Bh2[2][4], Bl2[2][4];
        #pragma unroll
        for (int mt = 0; mt < 4; mt++)
            ldsm4(Ar[mt][0], Ar[mt][1], Ar[mt][2], Ar[mt][3],
                  aOff + mt * (16 * ZROWB) + ko);
        #pragma unroll
        for (int pg = 0; pg < 2; pg++) {
            ldsm4(Bh2[pg][0], Bh2[pg][1], Bh2[pg][2], Bh2[pg][3],
                  bH + pg * (16 * ZROWB) + ko);
            ldsm4(Bl2[pg][0], Bl2[pg][1], Bl2[pg][2], Bl2[pg][3],
                  bL + pg * (16 * ZROWB) + ko);
        }
        #pragma unroll
        for (int mt = 0; mt < 4; mt++) {
            #pragma unroll
            for (int pg = 0; pg < 2; pg++) {
                #pragma unroll
                for (int hf = 0; hf < 2; hf++) {
                    int nt = pg * 2 + hf;
                    hmma(c[mt][nt], Ar[mt][0], Ar[mt][1], Ar[mt][2], Ar[mt][3],
                         Bh2[pg][hf * 2], Bh2[pg][hf * 2 + 1]);
                    hmma(c[mt][nt], Ar[mt][0], Ar[mt][1], Ar[mt][2], Ar[mt][3],
                         Bl2[pg][hf * 2], Bl2[pg][hf * 2 + 1]);
                }
            }
        }
    }
    __syncthreads();

    float* stg = (float*)(smem + ZOFF_ST);
    int g = lane >> 2, q = lane & 3;
    if (mg == 1) {   // stage Zm
        #pragma unroll
        for (int mt = 0; mt < 4; mt++) {
            #pragma unroll
            for (int nt = 0; nt < 4; nt++) {
                int o = mt * 16 + g;
                int sc = ng * 32 + nt * 8 + 2 * q;
                stg[o * 132 + sc]           = c[mt][nt][0];
                stg[o * 132 + sc + 1]       = c[mt][nt][1];
                stg[(o + 8) * 132 + sc]     = c[mt][nt][2];
                stg[(o + 8) * 132 + sc + 1] = c[mt][nt][3];
            }
        }
    }
    __syncthreads();
    if (mg == 0) {   // fold + write both parities
        #pragma unroll
        for (int mt = 0; mt < 4; mt++) {
            #pragma unroll
            for (int nt = 0; nt < 4; nt++) {
                int sc = ng * 32 + nt * 8 + 2 * q;       // even local s
                #pragma unroll
                for (int hh = 0; hh < 2; hh++) {
                    int o = mt * 16 + g + hh * 8;
                    float zp0 = c[mt][nt][hh * 2], zp1 = c[mt][nt][hh * 2 + 1];
                    float zm0 = stg[o * 132 + sc], zm1 = stg[o * 132 + sc + 1];
                    float s0 = zp0 + zm0, d0 = zp0 - zm0;
                    float s1 = zp1 + zm1, d1 = zp1 - zm1;
                    __half2 ev = __floats2half2_rn(s0, d1);
                    __half2 od = __floats2half2_rn(d0, s1);
                    int n = (b << 6) + o;
                    size_t sg = (size_t)(stile << 7) + sc;
                    *(unsigned*)&g_B[((size_t)(k * 2 + 0) * 128 + n) * 4096 + sg] =
                        *(unsigned*)&ev;
                    *(unsigned*)&g_B[((size_t)(k * 2 + 1) * 128 + n) * 4096 + sg] =
                        *(unsigned*)&od;
                }
            }
        }
    }
}

// ---------------------------------------------------------------------------
// HMMA polyphase Toeplitz GEMM. CTA = (row-tile rt, parity par, filter k).
// Block 128 (4 warps, 2x2), warp tile 64x64. A fragments loaded DIRECTLY from
// a reversed phi window in smem (one LDS.32 per fragment register); no A tile.
// B double-buffered via cp.async.
#define ROWB     144
#define TILEB    (128 * ROWB)          // 18432
#define GOFF_B   1536                  // after 2x640B reversed windows

__global__ void __launch_bounds__(128) k_gemm(float* __restrict__ out) {
    __shared__ char smem[GOFF_B + 2 * TILEB];
    unsigned sbu = smem_u32(smem);
    int tid = threadIdx.x, wid = tid >> 5, lane = tid & 31;
    int rt = 15 - (int)blockIdx.x;     // big tiles first
    int par = blockIdx.y, k = blockIdx.z;
    int tbase = (rt << 8) + par;
    int mg = wid >> 1, ng = wid & 1;   // warp tile: rows [mg*64,+64), cols [ng*64,+64)
    int g = lane >> 2, q = lane & 3;

    const unsigned short* phiArr = (const unsigned short*)(g_phi + (k << 12));
    const char* Bsrc = (const char*)(g_B + (size_t)(k * 2 + par) * 128 * 4096);

    // byte offset into reversed window for (mt=0, r=0, ks=0) fragment pair
    int iBase2 = 508 - 4 * (mg * 64 + g) + 4 * q;

    unsigned bLaneOff = (unsigned)((ng * 64 + (lane & 7) + ((lane >> 4) & 1) * 8) * ROWB
                                   + ((lane >> 3) & 1) * 16);

    // B copy: thread -> row tid, 8x16B
    const char* crowSrc = Bsrc + (size_t)tid * 8192;
    unsigned cdstBase = sbu + GOFF_B + tid * ROWB;

    int nch = 4 * (rt + 1);

    float c[4][8][4];
    #pragma unroll
    for (int i = 0; i < 4; i++)
        #pragma unroll
        for (int j = 0; j < 8; j++)
            #pragma unroll
            for (int qq = 0; qq < 4; qq++) c[i][j][qq] = 0.f;

    // prologue: prefetch B chunk 0 -> buf0
    #pragma unroll
    for (int s = 0; s < 8; s++) cp16(cdstBase + s * 16, crowSrc + s * 16);
    asm volatile("cp.async.commit_group;");

    for (int sbk = 0; sbk < nch; sbk++) {
        int p = sbk & 1;
        int Dd = tbase - (sbk << 6);

        // stage REVERSED phi window: winR[w] = phi[Dd+254-w], w in [0,318)
        unsigned short* win = (unsigned short*)(smem + p * 640);
        for (int w = tid; w < 318; w += 128) {
            int lag = Dd + 254 - w;
            win[w] = (lag >= 0 && lag < L) ? phiArr[lag] : (unsigned short)0;
        }
        __syncthreads();

        asm volatile("cp.async.wait_group 0;");   // B[p] arrived
        __syncthreads();

        // prefetch next B chunk into buf[p^1] (overlaps MMA below)
        if (sbk + 1 < nch) {
            const char* src = crowSrc + ((size_t)(sbk + 1) << 7);
            unsigned dst = cdstBase + (p ^ 1) * TILEB;
            #pragma unroll
            for (int s = 0; s < 8; s++) cp16(dst + s * 16, src + s * 16);
            asm volatile("cp.async.commit_group;");
        }

        // MMA phase: 4 k-steps of 16
        const char* wp0 = smem + p * 640 + iBase2;
        unsigned bB = sbu + GOFF_B + p * TILEB + bLaneOff;
        #pragma unroll
        for (int ks = 0; ks < 4; ks++) {
            const char* wp = wp0 + ks * 32;
            unsigned a[4][4];
            #pragma unroll
            for (int mt = 0; mt < 4; mt++) {
                a[mt][0] = *(const unsigned*)(wp - 64 * mt);
                a[mt][1] = *(const unsigned*)(wp - 64 * mt - 32);
                a[mt][2] = *(const unsigned*)(wp - 64 * mt + 16);
                a[mt][3] = *(const unsigned*)(wp - 64 * mt - 16);
            }
            unsigned Br[4][4];
            #pragma unroll
            for (int pg = 0; pg < 4; pg++)
                ldsm4(Br[pg][0], Br[pg][1], Br[pg][2], Br[pg][3],
                      bB + pg * (16 * ROWB) + ks * 32);
            #pragma unroll
            for (int mt = 0; mt < 4; mt++) {
                #pragma unroll
                for (int pg = 0; pg < 4; pg++) {
                    #pragma unroll
                    for (int hf = 0; hf < 2; hf++) {
                        hmma(c[mt][pg * 2 + hf],
                             a[mt][0], a[mt][1], a[mt][2], a[mt][3],
                             Br[pg][hf * 2], Br[pg][hf * 2 + 1]);
                    }
                }
            }
        }
    }

    // epilogue: t = tbase + 2*rowInTile; atomic-accumulate onto AR base
    #pragma unroll
    for (int mt = 0; mt < 4; mt++) {
        #pragma unroll
        for (int nt = 0; nt < 8; nt++) {
            int rowIn = mg * 64 + mt * 16 + g;
            int t = tbase + 2 * rowIn;
            int col = ng * 64 + nt * 8 + 2 * q;
            int b = col >> 6, o = col & 63;
            float* p0 = out + (((size_t)b * 4096 + t) * 64 + o);
            atomicAdd(p0,               c[mt][nt][0]);
            atomicAdd(p0 + 1,           c[mt][nt][1]);
            atomicAdd(p0 + 16 * 64,     c[mt][nt][2]);   // rowIn+8 -> t+16
            atomicAdd(p0 + 16 * 64 + 1, c[mt][nt][3]);
        }
    }
}

// ---------------------------------------------------------------------------
extern "C" void kernel_launch(void* const* d_in, const int* in_sizes, int n_in,
                              void* d_out, int out_size) {
    const float* x   = (const float*)d_in[0];   // (2,4096,64)
    const float* phi = (const float*)d_in[1];   // (4096,40)
    const float* M   = (const float*)d_in[2];   // (64,64,3)
    const float* Mp  = (const float*)d_in[3];   // (40,64,64)
    const float* Mm  = (const float*)d_in[4];   // (40,64,64)
    float* out = (float*)d_out;                 // (2,4096,64)

    cudaFuncSetAttribute(k_z, cudaFuncAttributeMaxDynamicSharedMemorySize, ZSMEM);
    cudaFuncSetAttribute(k_ar, cudaFuncAttributeMaxDynamicSharedMemorySize, AR_SMEM);

    k_prep<<<(NK * L + 255) / 256, 256>>>(phi);
    k_prep_m<<<(NK * 64 * 64 + 255) / 256, 256>>>(Mp, Mm);
    k_prep_x<<<(2 * L * 64 + 255) / 256, 256>>>(x);
    k_ar<<<dim3(32, 2), 256, AR_SMEM>>>(x, M, out);
    k_z<<<dim3(32, 2, NK), 256, ZSMEM>>>();
    k_gemm<<<dim3(16, 2, NK), 128>>>(out);
}

// round 17
// speedup vs baseline: 1.4896x; 1.4896x over previous
#include <cuda_runtime.h>
#include <cuda_fp16.h>

#define L    4096
#define NK   40

// ---------------------------------------------------------------------------
// Global scratch (static; no allocations)
__device__ __half g_phi[NK * L];                    // fp16 phi[lag], [k][lag]
__device__ __half g_Mh[NK * 128 * 64];              // [k][o-stack][d]: rows 0-63 Mp^T, 64-127 Mm^T
__device__ __half g_xh[2 * L * 64];                 // fp16 hi of x
__device__ __half g_xl[2 * L * 64];                 // fp16 lo of x
__device__ __half g_B[(size_t)NK * 2 * 128 * L];    // [k][par][n][s] fp16
// par=0: B'[s]  = (s even ? Zp+Zm : Zp-Zm)   (feeds even-t rows)
// par=1: B''[s] = (s even ? Zp-Zm : Zp+Zm)   (feeds odd-t rows)

// ---------------------------------------------------------------------------
__device__ __forceinline__ unsigned smem_u32(const void* p) {
    unsigned a;
    asm("{ .reg .u64 t; cvta.to.shared.u64 t, %1; cvt.u32.u64 %0, t; }" : "=r"(a) : "l"(p));
    return a;
}
__device__ __forceinline__ void ldsm4(unsigned& r0, unsigned& r1, unsigned& r2,
                                      unsigned& r3, unsigned addr) {
    asm volatile("ldmatrix.sync.aligned.m8n8.x4.shared.b16 {%0,%1,%2,%3}, [%4];"
                 : "=r"(r0), "=r"(r1), "=r"(r2), "=r"(r3) : "r"(addr));
}
__device__ __forceinline__ void hmma(float* c, unsigned a0, unsigned a1, unsigned a2,
                                     unsigned a3, unsigned b0, unsigned b1) {
    asm volatile(
        "mma.sync.aligned.m16n8k16.row.col.f32.f16.f16.f32 "
        "{%0,%1,%2,%3},{%4,%5,%6,%7},{%8,%9},{%0,%1,%2,%3};"
        : "+f"(c[0]), "+f"(c[1]), "+f"(c[2]), "+f"(c[3])
        : "r"(a0), "r"(a1), "r"(a2), "r"(a3), "r"(b0), "r"(b1));
}
__device__ __forceinline__ void cp16(unsigned dst, const void* src) {
    asm volatile("cp.async.ca.shared.global [%0], [%1], 16;" :: "r"(dst), "l"(src));
}

// ---------------------------------------------------------------------------
// prep: phi fp16
__global__ void k_prep(const float* __restrict__ phi) {
    int gid = blockIdx.x * 256 + threadIdx.x;
    if (gid >= NK * L) return;
    int k = gid >> 12, lag = gid & (L - 1);
    g_phi[(k << 12) + lag] = __float2half_rn(phi[lag * NK + k]);
}
// prep: M transposed+stacked fp16  (g_Mh[k][o][d]=Mp[k][d][o]; [k][64+o][d]=Mm)
__global__ void k_prep_m(const float* __restrict__ Mp, const float* __restrict__ Mm) {
    int gid = blockIdx.x * 256 + threadIdx.x;
    if (gid >= NK * 64 * 64) return;
    int k = gid >> 12, rem = gid & 4095, d = rem >> 6, o = rem & 63;
    g_Mh[((size_t)k * 128 + o) * 64 + d]      = __float2half_rn(Mp[gid]);
    g_Mh[((size_t)k * 128 + 64 + o) * 64 + d] = __float2half_rn(Mm[gid]);
}
// prep: x hi/lo fp16 split
__global__ void k_prep_x(const float* __restrict__ x) {
    int gid = blockIdx.x * 256 + threadIdx.x;
    if (gid >= 2 * L * 64) return;
    float v = x[gid];
    __half h = __float2half_rn(v);
    g_xh[gid] = h;
    g_xl[gid] = __float2half_rn(v - __half2float(h));
}

// ---------------------------------------------------------------------------
// AR term (initializes out), register-tiled: thread = 2t x 8o, float4 both ways.
// CTA = (t-block of 64, batch b); grid (64,2) = 128 CTAs.
#define AR_XROWS 66
#define AR_OFF_M (AR_XROWS * 64 * 4)                 // 16896
#define AR_SMEM  (AR_OFF_M + 3 * 64 * 64 * 4)        // 66048

__global__ void __launch_bounds__(256) k_ar(const float* __restrict__ x,
                                            const float* __restrict__ M,
                                            float* __restrict__ out) {
    extern __shared__ char arsm[];
    float* sx = (float*)arsm;                 // [66][64]
    float* sM = (float*)(arsm + AR_OFF_M);    // [(i*64+d)*64 + o]
    int tid = threadIdx.x;
    int tb = blockIdx.x, b = blockIdx.y;
    int tbase = tb << 6;

    // load M
    for (int idx = tid; idx < 64 * 64 * 3; idx += 256) {
        int o = idx / 192, rem = idx % 192, d = rem / 3, i = rem % 3;
        sM[(i * 64 + d) * 64 + o] = M[idx];
    }
    // load x rows tbase-2 .. tbase+63 (zero below 0)
    const float* xb = x + ((size_t)b << 18);
    for (int idx = tid; idx < AR_XROWS * 64; idx += 256) {
        int r = idx >> 6, c = idx & 63;
        int t = tbase + r - 2;
        sx[idx] = (t >= 0) ? xb[(t << 6) + c] : 0.f;
    }
    __syncthreads();

    int tx = tid & 7, ty = tid >> 3;          // o-block, t-block
    int trow0 = ty * 2, ocol = tx * 8;

    float4 acc[2][2];
    #pragma unroll
    for (int i = 0; i < 2; i++) {
        acc[i][0] = make_float4(0.f, 0.f, 0.f, 0.f);
        acc[i][1] = make_float4(0.f, 0.f, 0.f, 0.f);
    }

    const float4* sx4 = (const float4*)sx;
    const float4* sM4 = (const float4*)sM;

    #pragma unroll
    for (int i = 0; i < 3; i++) {
        #pragma unroll 4
        for (int db = 0; db < 16; db++) {
            float4 xv[2];
            #pragma unroll
            for (int tt = 0; tt < 2; tt++)
                xv[tt] = sx4[(trow0 + tt + 2 - i) * 16 + db];
            float4 mv[4][2];
            #pragma unroll
            for (int dd = 0; dd < 4; dd++) {
                int mrow = (i * 64 + db * 4 + dd) * 16 + tx * 2;
                mv[dd][0] = sM4[mrow];
                mv[dd][1] = sM4[mrow + 1];
            }
            #pragma unroll
            for (int tt = 0; tt < 2; tt++) {
                float xs0 = xv[tt].x, xs1 = xv[tt].y, xs2 = xv[tt].z, xs3 = xv[tt].w;
                #pragma unroll
                for (int v = 0; v < 2; v++) {
                    acc[tt][v].x += xs0 * mv[0][v].x + xs1 * mv[1][v].x
                                  + xs2 * mv[2][v].x + xs3 * mv[3][v].x;
                    acc[tt][v].y += xs0 * mv[0][v].y + xs1 * mv[1][v].y
                                  + xs2 * mv[2][v].y + xs3 * mv[3][v].y;
                    acc[tt][v].z += xs0 * mv[0][v].z + xs1 * mv[1][v].z
                                  + xs2 * mv[2][v].z + xs3 * mv[3][v].z;
                    acc[tt][v].w += xs0 * mv[0][v].w + xs1 * mv[1][v].w
                                  + xs2 * mv[2][v].w + xs3 * mv[3][v].w;
                }
            }
        }
    }

    #pragma unroll
    for (int tt = 0; tt < 2; tt++) {
        int t = tbase + trow0 + tt;
        float* p = out + ((((size_t)b << 12) + t) << 6) + ocol;
        *(float4*)p = acc[tt][0];
        *(float4*)(p + 4) = acc[tt][1];
    }
}

// ---------------------------------------------------------------------------
// HMMA Z build. CTA = (s-tile of 128, batch b, filter k). All operands
// pre-converted fp16 in global; cp.async into padded smem, MMA, parity-fold.
#define ZROWB   144
#define ZOFF_A  0
#define ZOFF_BH (128 * ZROWB)
#define ZOFF_BL (2 * 128 * ZROWB)
#define ZOFF_ST (3 * 128 * ZROWB)                // 64 x 132 fp32 stage
#define ZSMEM   (ZOFF_ST + 64 * 132 * 4)         // 89088

__global__ void __launch_bounds__(256) k_z() {
    extern __shared__ char smem[];
    unsigned sbu = smem_u32(smem);
    int tid = threadIdx.x, wid = tid >> 5, lane = tid & 31;
    int stile = blockIdx.x, b = blockIdx.y, k = blockIdx.z;
    int mg = wid >> 2, ng = wid & 3;   // warp: m-half (Zp/Zm), s-group of 32

    // cp.async: A (M stack), Bh, Bl (x split) — 128 rows x 128B each
    const char* srcA = (const char*)(g_Mh + (size_t)k * 8192);
    const char* srcH = (const char*)(g_xh + (((size_t)(b << 12) + (stile << 7)) << 6));
    const char* srcL = (const char*)(g_xl + (((size_t)(b << 12) + (stile << 7)) << 6));
    for (int i = tid; i < 1024; i += 256) {
        int row = i >> 3, seg = (i & 7) * 16;
        cp16(sbu + ZOFF_A + row * ZROWB + seg, srcA + row * 128 + seg);
        cp16(sbu + ZOFF_BH + row * ZROWB + seg, srcH + row * 128 + seg);
        cp16(sbu + ZOFF_BL + row * ZROWB + seg, srcL + row * 128 + seg);
    }
    asm volatile("cp.async.commit_group;");
    asm volatile("cp.async.wait_group 0;");
    __syncthreads();

    unsigned aOff = sbu + ZOFF_A + (unsigned)((mg * 64 + (lane & 15)) * ZROWB + (lane >> 4) * 16);
    unsigned bOff = (unsigned)((ng * 32 + (lane & 7) + ((lane >> 4) & 1) * 8) * ZROWB
                               + ((lane >> 3) & 1) * 16);
    unsigned bH = sbu + ZOFF_BH + bOff, bL = sbu + ZOFF_BL + bOff;

    float c[4][4][4];
    #pragma unroll
    for (int i = 0; i < 4; i++)
        #pragma unroll
        for (int j = 0; j < 4; j++)
            #pragma unroll
            for (int q = 0; q < 4; q++) c[i][j][q] = 0.f;

    #pragma unroll
    for (int ks = 0; ks < 4; ks++) {
        unsigned ko = ks * 32;
        unsigned Ar[4][4], Bh2[2][4], Bl2[2][4];
        #pragma unroll
        for (int mt = 0; mt < 4; mt++)
            ldsm4(Ar[mt][0], Ar[mt][1], Ar[mt][2], Ar[mt][3],
                  aOff + mt * (16 * ZROWB) + ko);
        #pragma unroll
        for (int pg = 0; pg < 2; pg++) {
            ldsm4(Bh2[pg][0], Bh2[pg][1], Bh2[pg][2], Bh2[pg][3],
                  bH + pg * (16 * ZROWB) + ko);
            ldsm4(Bl2[pg][0], Bl2[pg][1], Bl2[pg][2], Bl2[pg][3],
                  bL + pg * (16 * ZROWB) + ko);
        }
        #pragma unroll
        for (int mt = 0; mt < 4; mt++) {
            #pragma unroll
            for (int pg = 0; pg < 2; pg++) {
                #pragma unroll
                for (int hf = 0; hf < 2; hf++) {
                    int nt = pg * 2 + hf;
                    hmma(c[mt][nt], Ar[mt][0], Ar[mt][1], Ar[mt][2], Ar[mt][3],
                         Bh2[pg][hf * 2], Bh2[pg][hf * 2 + 1]);
                    hmma(c[mt][nt], Ar[mt][0], Ar[mt][1], Ar[mt][2], Ar[mt][3],
                         Bl2[pg][hf * 2], Bl2[pg][hf * 2 + 1]);
                }
            }
        }
    }
    __syncthreads();

    float* stg = (float*)(smem + ZOFF_ST);
    int g = lane >> 2, q = lane & 3;
    if (mg == 1) {   // stage Zm
        #pragma unroll
        for (int mt = 0; mt < 4; mt++) {
            #pragma unroll
            for (int nt = 0; nt < 4; nt++) {
                int o = mt * 16 + g;
                int sc = ng * 32 + nt * 8 + 2 * q;
                stg[o * 132 + sc]           = c[mt][nt][0];
                stg[o * 132 + sc + 1]       = c[mt][nt][1];
                stg[(o + 8) * 132 + sc]     = c[mt][nt][2];
                stg[(o + 8) * 132 + sc + 1] = c[mt][nt][3];
            }
        }
    }
    __syncthreads();
    if (mg == 0) {   // fold + write both parities
        #pragma unroll
        for (int mt = 0; mt < 4; mt++) {
            #pragma unroll
            for (int nt = 0; nt < 4; nt++) {
                int sc = ng * 32 + nt * 8 + 2 * q;       // even local s
                #pragma unroll
                for (int hh = 0; hh < 2; hh++) {
                    int o = mt * 16 + g + hh * 8;
                    float zp0 = c[mt][nt][hh * 2], zp1 = c[mt][nt][hh * 2 + 1];
                    float zm0 = stg[o * 132 + sc], zm1 = stg[o * 132 + sc + 1];
                    float s0 = zp0 + zm0, d0 = zp0 - zm0;
                    float s1 = zp1 + zm1, d1 = zp1 - zm1;
                    __half2 ev = __floats2half2_rn(s0, d1);
                    __half2 od = __floats2half2_rn(d0, s1);
                    int n = (b << 6) + o;
                    size_t sg = (size_t)(stile << 7) + sc;
                    *(unsigned*)&g_B[((size_t)(k * 2 + 0) * 128 + n) * 4096 + sg] =
                        *(unsigned*)&ev;
                    *(unsigned*)&g_B[((size_t)(k * 2 + 1) * 128 + n) * 4096 + sg] =
                        *(unsigned*)&od;
                }
            }
        }
    }
}

// ---------------------------------------------------------------------------
// HMMA polyphase Toeplitz GEMM (round-12 known-good). CTA = (rt, par, k).
// Tile rows m=0..127 are t = 256*rt + 2m + par. A[m][kk] = phi[Dd + 2m - kk].
// Single fp16 product, cp.async double-buffered B, smem A tile, 256 threads.
#define ROWB     144
#define TILEB    (128 * ROWB)          // 18432
#define OFF_A    768                   // 2 tiles: [buf]
#define OFF_B    (OFF_A + 2 * TILEB)   // 2 tiles: [buf]
#define SMEM_TOTAL (OFF_B + 2 * TILEB) // 74496

__global__ void __launch_bounds__(256, 2) k_gemm(float* __restrict__ out) {
    extern __shared__ char smem[];
    unsigned sbu = smem_u32(smem);
    int tid = threadIdx.x, wid = tid >> 5, lane = tid & 31;
    int rt = 15 - (int)blockIdx.x;     // big tiles first
    int par = blockIdx.y, k = blockIdx.z;
    int tbase = (rt << 8) + par;
    int mg = wid >> 1, ng = wid & 1;   // warp tile: rows [mg*32,+32), cols [ng*64,+64)

    const unsigned short* phiArr = (const unsigned short*)(g_phi + (k << 12));
    const char* Bsrc = (const char*)(g_B + (size_t)(k * 2 + par) * 128 * 4096);

    unsigned aLaneOff = (unsigned)((mg * 32 + (lane & 15)) * ROWB + (lane >> 4) * 16);
    unsigned bLaneOff = (unsigned)((ng * 64 + (lane & 7) + ((lane >> 4) & 1) * 8) * ROWB
                                   + ((lane >> 3) & 1) * 16);
    unsigned short* win = (unsigned short*)smem;   // 320 entries

    // B copy assignment: thread -> row (tid>>1), 4x16B at seg (tid&1)*64
    int crow = tid >> 1;
    int cseg = (tid & 1) * 64;
    size_t crowByte = (size_t)crow * 8192;
    unsigned cdstBase = sbu + OFF_B + crow * ROWB + cseg;

    int am = tid >> 1, ah2 = tid & 1;  // A build: row m, kk-half
    int wbase = 2 * am + 63 - ah2 * 32;

    int nch = 4 * (rt + 1);

    float c[2][8][4];
    #pragma unroll
    for (int i = 0; i < 2; i++)
        #pragma unroll
        for (int j = 0; j < 8; j++)
            #pragma unroll
            for (int q = 0; q < 4; q++) c[i][j][q] = 0.f;

    // prologue: prefetch B chunk 0 -> buf0
    {
        const char* src = Bsrc + crowByte + cseg;
        #pragma unroll
        for (int q = 0; q < 4; q++) cp16(cdstBase + q * 16, src + q * 16);
        asm volatile("cp.async.commit_group;");
    }

    for (int sbk = 0; sbk < nch; sbk++) {
        int p = sbk & 1;
        int Dd = tbase - (sbk << 6);

        // stage phi window [Dd-63, Dd+256] (320 fp16)
        for (int w = tid; w < 320; w += 256) {
            int lag = Dd - 63 + w;
            win[w] = (lag >= 0 && lag < L) ? phiArr[lag] : (unsigned short)0;
        }
        __syncthreads();

        // build A tile into Abuf[p]: A[m][kk] = win[2m - kk + 63]
        {
            char* Ah = smem + OFF_A + p * TILEB + am * ROWB + ah2 * 64;
            #pragma unroll
            for (int q = 0; q < 8; q++) {
                unsigned w0 = win[wbase - 4 * q];
                unsigned w1 = win[wbase - 4 * q - 1];
                unsigned w2 = win[wbase - 4 * q - 2];
                unsigned w3 = win[wbase - 4 * q - 3];
                uint2 h;
                h.x = w0 | (w1 << 16);
                h.y = w2 | (w3 << 16);
                *(uint2*)(Ah + q * 8) = h;
            }
        }

        asm volatile("cp.async.wait_group 0;");   // B[p] arrived
        __syncthreads();

        // prefetch next B chunk into buf[p^1] (overlaps MMA below)
        if (sbk + 1 < nch) {
            const char* src = Bsrc + crowByte + ((size_t)(sbk + 1) << 7) + cseg;
            unsigned dst = cdstBase + (p ^ 1) * TILEB;
            #pragma unroll
            for (int q = 0; q < 4; q++) cp16(dst + q * 16, src + q * 16);
            asm volatile("cp.async.commit_group;");
        }

        // MMA phase: 4 k-steps of 16
        unsigned aH = sbu + OFF_A + p * TILEB + aLaneOff;
        unsigned bB = sbu + OFF_B + p * TILEB + bLaneOff;
        #pragma unroll
        for (int ks = 0; ks < 4; ks++) {
            unsigned ko = ks * 32;
            unsigned Ahr[2][4], Br[4][4];
            #pragma unroll
            for (int mt = 0; mt < 2; mt++)
                ldsm4(Ahr[mt][0], Ahr[mt][1], Ahr[mt][2], Ahr[mt][3],
                      aH + mt * (16 * ROWB) + ko);
            #pragma unroll
            for (int pg = 0; pg < 4; pg++)
                ldsm4(Br[pg][0], Br[pg][1], Br[pg][2], Br[pg][3],
                      bB + pg * (16 * ROWB) + ko);
            #pragma unroll
            for (int mt = 0; mt < 2; mt++) {
                #pragma unroll
                for (int pg = 0; pg < 4; pg++) {
                    #pragma unroll
                    for (int hf = 0; hf < 2; hf++) {
                        hmma(c[mt][pg * 2 + hf],
                             Ahr[mt][0], Ahr[mt][1], Ahr[mt][2], Ahr[mt][3],
                             Br[pg][hf * 2], Br[pg][hf * 2 + 1]);
                    }
                }
            }
        }
    }

    // epilogue: t = tbase + 2*rowInTile; atomic-accumulate onto AR base
    int g = lane >> 2, tq = lane & 3;
    #pragma unroll
    for (int mt = 0; mt < 2; mt++) {
        #pragma unroll
        for (int nt = 0; nt < 8; nt++) {
            int rowIn = mg * 32 + mt * 16 + g;
            int t = tbase + 2 * rowIn;
            int col = ng * 64 + nt * 8 + 2 * tq;
            int b = col >> 6, o = col & 63;
            float* p0 = out + (((size_t)b * 4096 + t) * 64 + o);
            atomicAdd(p0,               c[mt][nt][0]);
            atomicAdd(p0 + 1,           c[mt][nt][1]);
            atomicAdd(p0 + 16 * 64,     c[mt][nt][2]);   // rowIn+8 -> t+16
            atomicAdd(p0 + 16 * 64 + 1, c[mt][nt][3]);
        }
    }
}

// ---------------------------------------------------------------------------
extern "C" void kernel_launch(void* const* d_in, const int* in_sizes, int n_in,
                              void* d_out, int out_size) {
    const float* x   = (const float*)d_in[0];   // (2,4096,64)
    const float* phi = (const float*)d_in[1];   // (4096,40)
    const float* M   = (const float*)d_in[2];   // (64,64,3)
    const float* Mp  = (const float*)d_in[3];   // (40,64,64)
    const float* Mm  = (const float*)d_in[4];   // (40,64,64)
    float* out = (float*)d_out;                 // (2,4096,64)

    cudaFuncSetAttribute(k_gemm, cudaFuncAttributeMaxDynamicSharedMemorySize, SMEM_TOTAL);
    cudaFuncSetAttribute(k_z, cudaFuncAttributeMaxDynamicSharedMemorySize, ZSMEM);
    cudaFuncSetAttribute(k_ar, cudaFuncAttributeMaxDynamicSharedMemorySize, AR_SMEM);

    k_prep<<<(NK * L + 255) / 256, 256>>>(phi);
    k_prep_m<<<(NK * 64 * 64 + 255) / 256, 256>>>(Mp, Mm);
    k_prep_x<<<(2 * L * 64 + 255) / 256, 256>>>(x);
    k_ar<<<dim3(64, 2), 256, AR_SMEM>>>(x, M, out);
    k_z<<<dim3(32, 2, NK), 256, ZSMEM>>>();
    k_gemm<<<dim3(16, 2, NK), 256, SMEM_TOTAL>>>(out);
}